// round 11
// baseline (speedup 1.0000x reference)
#include <cuda_runtime.h>
#include <cuda_fp16.h>
#include <cstdint>

#define TB_ 131072
#define B_  32

// ---------------- device scratch (no allocation allowed) ----------------
__device__ float g_hbre[B_ * 512];             // [b][nt*128 + hl*4 + q]
__device__ uint2 g_wfrag[4 * 16 * 8 * 32];     // [nt][NF(16)][ks(8)][lane] -> {b0,b1}
// A frags for 64-row tiles: [mt64(2048)][ks(8)][rg(4)][lane(32)] -> uint4
__device__ uint4 g_afrag[2048 * 8 * 4 * 32];   // 33.5 MB

// ---------------- helpers ----------------
__device__ __forceinline__ float tanh_ap(float x) {
    float y; asm("tanh.approx.f32 %0, %1;" : "=f"(y) : "f"(x)); return y;
}
__device__ __forceinline__ float sig_ap(float x) { return fmaf(tanh_ap(x * 0.5f), 0.5f, 0.5f); }

// ---------------- fused prep kernel ----------------
// blocks [0,64):     Hb = h0 @ W_hh^T + b_ih + b_hh (gate-interleaved layout)
// blocks [64,128):   W_ih -> fp16 B-fragment-major with in-lane gate mapping
// blocks [128,8320): input fp32 -> fp16 A-fragment-major (64-row tiles)
__global__ void prep_all(const float* __restrict__ input, const float* __restrict__ h0,
                         const float* __restrict__ W_hh, const float* __restrict__ b_ih,
                         const float* __restrict__ b_hh, const float* __restrict__ W_ih) {
    const int bx = blockIdx.x, tid = threadIdx.x;
    if (bx < 64) {
        int idx = bx * 256 + tid;
        int b = idx & 31, g = idx >> 5;
        const float4* wv = (const float4*)(W_hh + g * 128);
        const float4* hv = (const float4*)(h0 + b * 128);
        float s0 = b_ih[g] + b_hh[g], s1 = 0.f, s2 = 0.f, s3 = 0.f;
#pragma unroll
        for (int k = 0; k < 32; k++) {
            float4 w = wv[k], h = hv[k];
            s0 += w.x * h.x; s1 += w.y * h.y; s2 += w.z * h.z; s3 += w.w * h.w;
        }
        float s = (s0 + s1) + (s2 + s3);
        int q = g >> 7, rest = g & 127, nt = rest >> 5, hl = rest & 31;
        g_hbre[b * 512 + nt * 128 + hl * 4 + q] = s;
    } else if (bx < 128) {
        // B frag col mapping: lane owns all 4 gates of head wn*8 + j*4 + (lane&3)
        int idx = (bx - 64) * 256 + tid;          // [nt][NF][ks][lane]
        int l = idx & 31, ks = (idx >> 5) & 7, NF = (idx >> 8) & 15, nt = idx >> 12;
        int c = l >> 2, tt = l & 3;               // frag col group, k-quarter
        int wn = NF >> 2, nf = NF & 3;
        int head32 = wn * 8 + ((nf >> 1) << 2) + (c >> 1);
        int gate   = (nf & 1) * 2 + (c & 1);
        int g = gate * 128 + nt * 32 + head32;
        int k0 = ks * 16 + tt * 2;
        const float* wr = W_ih + g * 128;
        __half2 b0 = __floats2half2_rn(wr[k0], wr[k0 + 1]);
        __half2 b1 = __floats2half2_rn(wr[k0 + 8], wr[k0 + 9]);
        g_wfrag[idx] = make_uint2(*(uint32_t*)&b0, *(uint32_t*)&b1);
    } else {
        // A frag (row-major m16n8k16): rows mt64*64 + rg*16 + {g2, g2+8}
        int ci = (bx - 128) * 256 + tid;
        int lane = ci & 31;
        int rg   = (ci >> 5) & 3;
        int ks   = (ci >> 7) & 7;
        int mt   = ci >> 10;
        int g2 = lane >> 2, t2 = (lane & 3) * 2;
        const float* ip = input + ((size_t)mt * 64 + rg * 16 + g2) * 128 + ks * 16 + t2;
        float2 x00 = *(const float2*)(ip);
        float2 x10 = *(const float2*)(ip + 8 * 128);
        float2 x01 = *(const float2*)(ip + 8);
        float2 x11 = *(const float2*)(ip + 8 * 128 + 8);
        __half2 a0 = __floats2half2_rn(x00.x, x00.y);
        __half2 a1 = __floats2half2_rn(x10.x, x10.y);
        __half2 a2 = __floats2half2_rn(x01.x, x01.y);
        __half2 a3 = __floats2half2_rn(x11.x, x11.y);
        g_afrag[ci] = make_uint4(*(uint32_t*)&a0, *(uint32_t*)&a1,
                                 *(uint32_t*)&a2, *(uint32_t*)&a3);
    }
}

// ---------------- main kernel ----------------
#define SMEM_B   0                 // 32768 : B frags (uint2 x 4096)
#define SMEM_HB  32768             // 16896 : HBs [32][132] f32 (hl*4+q packed float4)
#define SMEM_C0  49664             // 4224  : c0   [32][33]
#define SMEM_NZ  53888             // 4224  : noise[32][33]
#define SMEM_TOT 58112             // 56.75 KB -> 3 CTAs/SM

__global__ __launch_bounds__(256, 3)
void lstm_mma(const float* __restrict__ c0, const float* __restrict__ noise,
              float* __restrict__ out) {
    extern __shared__ char sm[];
    uint2* Bs  = (uint2*)(sm + SMEM_B);
    float* HBs = (float*)(sm + SMEM_HB);
    float* C0s = (float*)(sm + SMEM_C0);
    float* NZs = (float*)(sm + SMEM_NZ);

    const int tid = threadIdx.x;
    const int wid = tid >> 5, lane = tid & 31;
    const int nt = blockIdx.x & 3, grp = blockIdx.x >> 2;   // grp 0..511
    const int wm = wid & 1, wn = wid >> 1;                  // 2m x 4n (32-row x 32-col warps)

    // ---- stage B fragments, HB, c0, noise (once per CTA) ----
    {
        const uint2* src = g_wfrag + nt * 4096;
        for (int i = tid; i < 4096; i += 256) Bs[i] = src[i];
        for (int i = tid; i < 4096; i += 256) {
            int b = i >> 7, c = i & 127;
            HBs[b * 132 + c] = g_hbre[b * 512 + nt * 128 + c];
        }
        for (int i = tid; i < 1024; i += 256) {
            int b = i >> 5, hl = i & 31;
            C0s[b * 33 + hl] = c0[b * 128 + nt * 32 + hl];
            NZs[b * 33 + hl] = noise[b * 128 + nt * 32 + hl];
        }
    }
    __syncthreads();                                   // only barrier in the kernel

    const int t = lane & 3, g = lane >> 2;

    for (int tile = 0; tile < 4; tile++) {
        const int mt64 = grp * 4 + tile;               // 64-row tile, 0..2047
        const int r0 = mt64 * 64;
        // frag(ks, mf) at Ag[(ks*4 + mf)*32]; rg = wm*2 + mf
        const uint4* Ag = g_afrag + ((size_t)mt64 * 32 + wm * 2) * 32 + lane;

        float acc[2][4][4];
#pragma unroll
        for (int mf = 0; mf < 2; mf++)
#pragma unroll
            for (int nf = 0; nf < 4; nf++)
#pragma unroll
                for (int r = 0; r < 4; r++) acc[mf][nf][r] = 0.f;

        uint4 af[2][2];
        af[0][0] = Ag[0];
        af[0][1] = Ag[32];

#pragma unroll
        for (int ks = 0; ks < 8; ks++) {
            if (ks < 7) {                              // prefetch next ks
                af[(ks + 1) & 1][0] = Ag[((ks + 1) * 4 + 0) * 32];
                af[(ks + 1) & 1][1] = Ag[((ks + 1) * 4 + 1) * 32];
            }
            uint2 bfr[4];
#pragma unroll
            for (int nf = 0; nf < 4; nf++)
                bfr[nf] = Bs[((wn * 4 + nf) * 8 + ks) * 32 + lane];
#pragma unroll
            for (int mf = 0; mf < 2; mf++) {
                uint4 a = af[ks & 1][mf];
#pragma unroll
                for (int nf = 0; nf < 4; nf++) {
                    asm volatile(
                        "mma.sync.aligned.m16n8k16.row.col.f32.f16.f16.f32 "
                        "{%0,%1,%2,%3}, {%4,%5,%6,%7}, {%8,%9}, {%0,%1,%2,%3};"
                        : "+f"(acc[mf][nf][0]), "+f"(acc[mf][nf][1]),
                          "+f"(acc[mf][nf][2]), "+f"(acc[mf][nf][3])
                        : "r"(a.x), "r"(a.y), "r"(a.z), "r"(a.w),
                          "r"(bfr[nf].x), "r"(bfr[nf].y));
                }
            }
        }

        // ---- fused LSTM epilogue: fully in-lane, no shfl, no smem stage ----
#pragma unroll
        for (int mf = 0; mf < 2; mf++) {
#pragma unroll
            for (int j = 0; j < 2; j++) {              // head pair
                const int hl = wn * 8 + j * 4 + t;
#pragma unroll
                for (int r = 0; r < 2; r++) {          // row g / g+8
                    const int row = wm * 32 + mf * 16 + g + r * 8;
                    const int b = row & 31;
                    float4 hb = *(float4*)(HBs + b * 132 + hl * 4);
                    float gi = acc[mf][2 * j][2 * r]     + hb.x;
                    float gf = acc[mf][2 * j][2 * r + 1] + hb.y;
                    float gg = acc[mf][2 * j + 1][2 * r]     + hb.z;
                    float go = acc[mf][2 * j + 1][2 * r + 1] + hb.w;
                    float si = sig_ap(gi), sf = sig_ap(gf), so = sig_ap(go);
                    float tg = tanh_ap(gg);
                    float cc = sf * C0s[b * 33 + hl] + si * tg;
                    float hv = so * tanh_ap(cc) + NZs[b * 33 + hl];
                    const int gr = r0 + row;
                    out[(size_t)gr * 128 + nt * 32 + hl] = hv;
                    if (gr >= TB_ - 32) {              // last timestep rows
                        size_t base = (size_t)TB_ * 128 + (size_t)b * 128 + nt * 32 + hl;
                        out[base] = hv;                // h_last
                        out[base + 32 * 128] = cc;     // c_last
                    }
                }
            }
        }
    }
}

// ---------------- launch ----------------
extern "C" void kernel_launch(void* const* d_in, const int* in_sizes, int n_in,
                              void* d_out, int out_size) {
    const float* input = (const float*)d_in[0];
    const float* h0    = (const float*)d_in[1];
    const float* c0    = (const float*)d_in[2];
    const float* noise = (const float*)d_in[3];
    const float* W_ih  = (const float*)d_in[4];
    const float* W_hh  = (const float*)d_in[5];
    const float* b_ih  = (const float*)d_in[6];
    const float* b_hh  = (const float*)d_in[7];
    float* out = (float*)d_out;

    prep_all<<<128 + 8192, 256>>>(input, h0, W_hh, b_ih, b_hh, W_ih);

    cudaFuncSetAttribute(lstm_mma, cudaFuncAttributeMaxDynamicSharedMemorySize, SMEM_TOT);
    lstm_mma<<<2048, 256, SMEM_TOT>>>(c0, noise, out);
}

// round 13
// speedup vs baseline: 1.2949x; 1.2949x over previous
#include <cuda_runtime.h>
#include <cuda_fp16.h>
#include <cstdint>

#define TB_ 131072
#define B_  32

// ---------------- device scratch (no allocation allowed) ----------------
__device__ float g_hbre[B_ * 512];             // [b][nt*128 + hl*4 + q]
__device__ uint4 g_wfrag4[4 * 8 * 8 * 32];     // [nt][ks][jj][lane] -> {bA0,bA1,bB0,bB1}
// A frags for 64-row tiles: [mt64(2048)][ks(8)][rg(4)][lane(32)] -> uint4
__device__ uint4 g_afrag[2048 * 8 * 4 * 32];   // 33.5 MB

// ---------------- helpers ----------------
__device__ __forceinline__ float tanh_ap(float x) {
    float y; asm("tanh.approx.f32 %0, %1;" : "=f"(y) : "f"(x)); return y;
}

// ---------------- fused prep kernel ----------------
// blocks [0,64):    Hb = h0 @ W_hh^T + b_ih + b_hh (gate-interleaved layout)
// blocks [64,96):   W_ih -> fp16 B-frag uint4 pairs, in-lane gate/head mapping
// blocks [96,8288): input fp32 -> fp16 A-fragment-major (64-row tiles)
__global__ void prep_all(const float* __restrict__ input, const float* __restrict__ h0,
                         const float* __restrict__ W_hh, const float* __restrict__ b_ih,
                         const float* __restrict__ b_hh, const float* __restrict__ W_ih) {
    const int bx = blockIdx.x, tid = threadIdx.x;
    if (bx < 64) {
        int idx = bx * 256 + tid;
        int b = idx & 31, g = idx >> 5;
        const float4* wv = (const float4*)(W_hh + g * 128);
        const float4* hv = (const float4*)(h0 + b * 128);
        float s0 = b_ih[g] + b_hh[g], s1 = 0.f, s2 = 0.f, s3 = 0.f;
#pragma unroll
        for (int k = 0; k < 32; k++) {
            float4 w = wv[k], h = hv[k];
            s0 += w.x * h.x; s1 += w.y * h.y; s2 += w.z * h.z; s3 += w.w * h.w;
        }
        float s = (s0 + s1) + (s2 + s3);
        int q = g >> 7, rest = g & 127, nt = rest >> 5, hl = rest & 31;
        g_hbre[b * 512 + nt * 128 + hl * 4 + q] = s;
    } else if (bx < 96) {
        // col n of nf-block: gate = (nf&1)*2 + (n&1); head-local = (n>>1)*2 + (nf>>1)
        int idx = (bx - 64) * 256 + tid;           // 0..8191 = [nt][ks][jj][lane]
        int lane = idx & 31, jj = (idx >> 5) & 7, ks = (idx >> 8) & 7, nt = idx >> 11;
        int n = lane >> 2, tt = lane & 3;
        int k0 = ks * 16 + tt * 2;
        uint32_t v[4];
#pragma unroll
        for (int s = 0; s < 2; s++) {
            int NF = jj * 2 + s;
            int wn = NF >> 2, nf = NF & 3;
            int gate  = (nf & 1) * 2 + (n & 1);
            int headl = (n >> 1) * 2 + (nf >> 1);
            int gw = gate * 128 + nt * 32 + wn * 8 + headl;
            const float* wr = W_ih + gw * 128;
            __half2 b0 = __floats2half2_rn(wr[k0], wr[k0 + 1]);
            __half2 b1 = __floats2half2_rn(wr[k0 + 8], wr[k0 + 9]);
            v[s * 2 + 0] = *(uint32_t*)&b0;
            v[s * 2 + 1] = *(uint32_t*)&b1;
        }
        g_wfrag4[idx] = make_uint4(v[0], v[1], v[2], v[3]);
    } else {
        // A frag (row-major m16n8k16): rows mt64*64 + rg*16 + {g2, g2+8}
        int ci = (bx - 96) * 256 + tid;
        int lane = ci & 31;
        int rg   = (ci >> 5) & 3;
        int ks   = (ci >> 7) & 7;
        int mt   = ci >> 10;
        int g2 = lane >> 2, t2 = (lane & 3) * 2;
        const float* ip = input + ((size_t)mt * 64 + rg * 16 + g2) * 128 + ks * 16 + t2;
        float2 x00 = *(const float2*)(ip);
        float2 x10 = *(const float2*)(ip + 8 * 128);
        float2 x01 = *(const float2*)(ip + 8);
        float2 x11 = *(const float2*)(ip + 8 * 128 + 8);
        __half2 a0 = __floats2half2_rn(x00.x, x00.y);
        __half2 a1 = __floats2half2_rn(x10.x, x10.y);
        __half2 a2 = __floats2half2_rn(x01.x, x01.y);
        __half2 a3 = __floats2half2_rn(x11.x, x11.y);
        g_afrag[ci] = make_uint4(*(uint32_t*)&a0, *(uint32_t*)&a1,
                                 *(uint32_t*)&a2, *(uint32_t*)&a3);
    }
}

// ---------------- main kernel ----------------
__global__ __launch_bounds__(256, 2)
void lstm_mma(const float* __restrict__ c0, const float* __restrict__ noise,
              float* __restrict__ out) {
    __shared__ uint4 Bs[2048];                    // 32 KB static

    const int tid = threadIdx.x;
    const int wid = tid >> 5, lane = tid & 31;
    const int nt = blockIdx.x & 3, grp = blockIdx.x >> 2;   // grp 0..511
    const int wm = wid & 1, wn = wid >> 1;                  // 2m x 4n (32x32 warp tiles)
    const int g_row = lane >> 2, t = lane & 3;

    // ---- stage B fragments (only smem use) ----
    {
        const uint4* src = g_wfrag4 + nt * 2048;
        for (int i = tid; i < 2048; i += 256) Bs[i] = src[i];
    }

    // ---- register-cache epilogue constants (tile-invariant per lane) ----
    float4 hbC[4][2];
    float  c0C[4][2], nzC[4][2];
#pragma unroll
    for (int mi = 0; mi < 4; mi++) {
        const int b = mi * 8 + g_row;
#pragma unroll
        for (int j = 0; j < 2; j++) {
            const int hl = wn * 8 + t * 2 + j;
            float4 hb = *(const float4*)(g_hbre + b * 512 + nt * 128 + hl * 4);
            hbC[mi][j] = make_float4(hb.x * 0.5f, hb.y * 0.5f, hb.z, hb.w * 0.5f);
            c0C[mi][j] = c0[b * 128 + nt * 32 + hl];
            nzC[mi][j] = noise[b * 128 + nt * 32 + hl];
        }
    }
    __syncthreads();

    // A frag base: [mt64][ks(8)][rg(4)][lane]; rg = wm*2 + mf; tile stride 1024
    const uint4* Ag = g_afrag + ((size_t)(grp * 4) * 32 + wm * 2) * 32 + lane;

    uint4 af[2][2];
    af[0][0] = Ag[0];
    af[0][1] = Ag[32];

    for (int tile = 0; tile < 4; tile++) {
        const int r0 = (grp * 4 + tile) * 64;

        float acc[2][4][4];
#pragma unroll
        for (int mf = 0; mf < 2; mf++)
#pragma unroll
            for (int nf = 0; nf < 4; nf++)
#pragma unroll
                for (int r = 0; r < 4; r++) acc[mf][nf][r] = 0.f;

#pragma unroll
        for (int ks = 0; ks < 8; ks++) {
            if (ks < 7) {                          // prefetch next ks (dist 1)
                af[(ks + 1) & 1][0] = Ag[((ks + 1) * 4 + 0) * 32];
                af[(ks + 1) & 1][1] = Ag[((ks + 1) * 4 + 1) * 32];
            } else if (tile < 3) {                 // prefetch next tile ks0 -> buf 0
                af[0][0] = Ag[1024 + 0 * 32];
                af[0][1] = Ag[1024 + 1 * 32];
            }
            const uint4 q0 = Bs[(ks * 8 + wn * 2 + 0) * 32 + lane];
            const uint4 q1 = Bs[(ks * 8 + wn * 2 + 1) * 32 + lane];
#pragma unroll
            for (int mf = 0; mf < 2; mf++) {
                uint4 a = af[ks & 1][mf];
#define MMA_(ACC, BX, BY) \
                asm volatile("mma.sync.aligned.m16n8k16.row.col.f32.f16.f16.f32 " \
                    "{%0,%1,%2,%3}, {%4,%5,%6,%7}, {%8,%9}, {%0,%1,%2,%3};" \
                    : "+f"(ACC[0]), "+f"(ACC[1]), "+f"(ACC[2]), "+f"(ACC[3]) \
                    : "r"(a.x), "r"(a.y), "r"(a.z), "r"(a.w), "r"(BX), "r"(BY))
                MMA_(acc[mf][0], q0.x, q0.y);
                MMA_(acc[mf][1], q0.z, q0.w);
                MMA_(acc[mf][2], q1.x, q1.y);
                MMA_(acc[mf][3], q1.z, q1.w);
#undef MMA_
            }
        }
        Ag += 1024;

        // ---- fused LSTM epilogue: all-register, STG.64 pairs ----
#pragma unroll
        for (int mf = 0; mf < 2; mf++) {
#pragma unroll
            for (int r = 0; r < 2; r++) {
                const int mi = mf * 2 + r;
                const int row = wm * 32 + mf * 16 + g_row + r * 8;
                float hv2[2], cc2[2];
#pragma unroll
                for (int j = 0; j < 2; j++) {
                    float4 hb = hbC[mi][j];
                    float ti = tanh_ap(fmaf(acc[mf][2 * j][2 * r],     0.5f, hb.x));
                    float tf = tanh_ap(fmaf(acc[mf][2 * j][2 * r + 1], 0.5f, hb.y));
                    float tg = tanh_ap(acc[mf][2 * j + 1][2 * r] + hb.z);
                    float to = tanh_ap(fmaf(acc[mf][2 * j + 1][2 * r + 1], 0.5f, hb.w));
                    float si = fmaf(ti, 0.5f, 0.5f);
                    float sf = fmaf(tf, 0.5f, 0.5f);
                    float so = fmaf(to, 0.5f, 0.5f);
                    float cc = sf * c0C[mi][j] + si * tg;
                    float hv = fmaf(so, tanh_ap(cc), nzC[mi][j]);
                    hv2[j] = hv; cc2[j] = cc;
                }
                const int gr = r0 + row;
                *(float2*)(out + (size_t)gr * 128 + nt * 32 + wn * 8 + t * 2) =
                    make_float2(hv2[0], hv2[1]);
                if (gr >= TB_ - 32) {              // last timestep rows
                    size_t base = (size_t)TB_ * 128 + (size_t)(mi * 8 + g_row) * 128
                                + nt * 32 + wn * 8 + t * 2;
                    *(float2*)(out + base)        = make_float2(hv2[0], hv2[1]);
                    *(float2*)(out + base + 4096) = make_float2(cc2[0], cc2[1]);
                }
            }
        }
    }
}

// ---------------- launch ----------------
extern "C" void kernel_launch(void* const* d_in, const int* in_sizes, int n_in,
                              void* d_out, int out_size) {
    const float* input = (const float*)d_in[0];
    const float* h0    = (const float*)d_in[1];
    const float* c0    = (const float*)d_in[2];
    const float* noise = (const float*)d_in[3];
    const float* W_ih  = (const float*)d_in[4];
    const float* W_hh  = (const float*)d_in[5];
    const float* b_ih  = (const float*)d_in[6];
    const float* b_hh  = (const float*)d_in[7];
    float* out = (float*)d_out;

    prep_all<<<96 + 8192, 256>>>(input, h0, W_hh, b_ih, b_hh, W_ih);
    lstm_mma<<<2048, 256>>>(c0, noise, out);
}